// round 7
// baseline (speedup 1.0000x reference)
#include <cuda_runtime.h>

#define N_PH  1024
#define IMG   256
#define NPIX  (IMG * IMG)
#define TW    32          // tile width  (pixels)
#define TH    8           // tile height (pixels)
#define CAP   512         // max survivors per tile (analysis bound ~150)

// Constants from the reference
#define C_SPREAD_INV  (1.0f / 0.000675f)
#define C_R2S         0.5f
#define C_SLOPE       19152642.5f
#define C_HALF        1.057e-07f
#define C_RHEO        2.39e-05f
#define C_PWF         (0.00017f * 300.0f)
#define C_ISCALE      8e-05f
#define HALF_LOG2E    0.72134752f   // log2(e)/2 ; exp(-d2/2s2) = exp2(-HALF_LOG2E*d2/s2)

// Single-instruction exp2 (MUFU.EX2), independent of compiler fast-math flags.
__device__ __forceinline__ float ex2_approx(float x) {
    float r;
    asm("ex2.approx.f32 %0, %1;" : "=f"(r) : "f"(x));
    return r;
}

__global__ void __launch_bounds__(256)
fused_kernel(const float* __restrict__ stim,
             const float* __restrict__ vx,
             const float* __restrict__ vy,
             const float* __restrict__ Marr,
             const float* __restrict__ px,
             const float* __restrict__ py,
             const int*   __restrict__ idx,
             float*       __restrict__ out)
{
    __shared__ float4 sh[CAP];
    __shared__ int    cnt;

    const int tid  = threadIdx.x;
    const int bx   = blockIdx.x;           // 0..511
    const int b    = bx >> 8;              // batch
    const int tile = bx & 255;             // 8 x-tiles * 32 y-tiles
    const int tx0  = (tile & 7)  * TW;
    const int ty0  = (tile >> 3) * TH;

    if (tid == 0) cnt = 0;

    // fov = px.max() = last element of ascending linspace
    const float fov = px[NPIX - 1];
    const float d2p = (float)IMG / (2.0f * fov);   // deg2pix

    // Scaled pixel coordinate of column w: px[w]*d2p == w*(256/255) - 128 (±ulp).
    // Approximation error (~1e-3 px) is absorbed by the 6-sigma footprint.
    const float PSTEP = 256.0f / 255.0f;
    const float bxlo = tx0 * PSTEP - 128.0f;
    const float bxhi = (tx0 + TW - 1) * PSTEP - 128.0f;
    const float bylo = ty0 * PSTEP - 128.0f;
    const float byhi = (ty0 + TH - 1) * PSTEP - 128.0f;

    // q = s*qk equals sigma_px^2 * M^2 before the >=1 clamp
    const float qk = C_ISCALE * C_SPREAD_INV * (C_R2S * d2p) * (C_R2S * d2p);

    __syncthreads();   // cnt visible

    // ---- Phase 1: compact the phosphenes whose footprint touches this tile ----
    // Division/sqrt-free cull; transcendentals only on the survivor path.
    const float* stimb = stim + b * N_PH;
    for (int n = tid; n < N_PH; n += 256) {
        const float s   = stimb[idx[n]];
        const float cxs = vx[n] * d2p;
        const float cys = vy[n] * d2p;
        const float Mv  = Marr[n];
        const float M2  = Mv * Mv;
        const float q   = s * qk;
        const float sden = fmaxf(q, M2);      // sigma_px^2 = sden / M2 (>=1 clamp)

        // 6-sigma footprint: dd2 > 36*sigma^2  <=>  dd2*M2 > 36*max(q, M2)
        const float ddx = fmaxf(fmaxf(bxlo - cxs, cxs - bxhi), 0.0f);
        const float ddy = fmaxf(fmaxf(bylo - cys, cys - byhi), 0.0f);
        const float dd2 = fmaf(ddx, ddx, ddy * ddy);
        if (dd2 * M2 > 36.0f * sden) continue;

        // Survivor-only transcendentals (brightness weight, x2 scale folded in)
        const float I    = s * C_ISCALE;
        const float Ieff = fmaxf(I - C_RHEO, 0.0f);
        const float t    = C_SLOPE * (Ieff * C_PWF - C_HALF);
        const float Bw2  = __fdividef(2.0f, 1.0f + __expf(-t));
        const float m    = -HALF_LOG2E * __fdividef(M2, sden);

        const int p = atomicAdd(&cnt, 1);
        if (p < CAP) sh[p] = make_float4(cxs, cys, m, Bw2);
    }
    __syncthreads();

    // ---- Phase 2: one pixel per thread, register accumulation ----
    const int w = tx0 + (tid & 31);
    const int h = ty0 + (tid >> 5);
    // Exact grid values (match reference bit-level coordinates):
    // px[y][x] depends only on x (row 0); py[y][x] only on y (col 0).
    const float pxs = px[w] * d2p;
    const float pys = py[h * IMG] * d2p;

    const int nsv = min(cnt, CAP);
    float acc = 0.0f;
    #pragma unroll 4
    for (int i = 0; i < nsv; i++) {
        const float4 f = sh[i];
        const float dx = pxs - f.x;
        const float dy = pys - f.y;
        const float d2 = fmaf(dx, dx, dy * dy);
        acc = fmaf(f.w, ex2_approx(d2 * f.z), acc);   // single-MUFU gaussian
    }

    out[b * NPIX + h * IMG + w] = fminf(acc, 1.0f);  // acc >= 0 always
}

extern "C" void kernel_launch(void* const* d_in, const int* in_sizes, int n_in,
                              void* d_out, int out_size)
{
    const float* stim = (const float*)d_in[0];   // [2,32,32]
    const float* vx   = (const float*)d_in[1];   // [1024]
    const float* vy   = (const float*)d_in[2];   // [1024]
    const float* M    = (const float*)d_in[3];   // [1024]
    const float* px   = (const float*)d_in[4];   // [256,256]
    const float* py   = (const float*)d_in[5];   // [256,256]
    const int*   idx  = (const int*)  d_in[6];   // [1024]
    float* out = (float*)d_out;                  // [2,1,256,256]

    fused_kernel<<<2 * (IMG / TW) * (IMG / TH), 256>>>(stim, vx, vy, M, px, py, idx, out);
}